// round 15
// baseline (speedup 1.0000x reference)
#include <cuda_runtime.h>
#include <math_constants.h>

#define B_SZ 16
#define N_PTS 4096
#define K_NN 20
#define CO 64
#define KNN_BLOCKS 128
#define NVALS 27
#define CAP 32          // per-lane smem stack capacity (4B slots)
#define SLACK 2e-3f

// ---------------- scratch (static device allocations, allowed) ----------------
__device__ int            g_idx[B_SZ * N_PTS * K_NN];     // 5.24 MB
__device__ float4         g_sorted[B_SZ * N_PTS];         // 4 MB  (sorted by x)
__device__ unsigned short g_oidx[B_SZ * N_PTS];           // sorted pos -> orig idx
__device__ unsigned short g_map[B_SZ * N_PTS];            // orig idx  -> sorted pos
__device__ double         g_part[KNN_BLOCKS * NVALS];
__device__ float          g_scale[CO];
__device__ float          g_shift[CO];

// packed f32x2 helpers (sm_100+ PTX)
__device__ __forceinline__ unsigned long long pack2(float lo, float hi) {
    unsigned long long r;
    asm("mov.b64 %0, {%1,%2};" : "=l"(r) : "f"(lo), "f"(hi));
    return r;
}
__device__ __forceinline__ void unpack2(unsigned long long v, float& lo, float& hi) {
    asm("mov.b64 {%0,%1}, %2;" : "=f"(lo), "=f"(hi) : "l"(v));
}
#define FMA2(d, a, b, c) \
    asm("fma.rn.f32x2 %0, %1, %2, %3;" : "=l"(d) : "l"(a), "l"(b), "l"(c))

// float bits -> order-preserving u32 key (handles negatives)
__device__ __forceinline__ unsigned fkey(float f) {
    unsigned b = __float_as_uint(f);
    return b ^ ((unsigned)((int)b >> 31) | 0x80000000u);
}
__device__ __forceinline__ float fkey_inv(unsigned t) {
    unsigned b = (t & 0x80000000u) ? (t ^ 0x80000000u) : ~t;
    return __uint_as_float(b);
}

// sorted top-20 as u64 keys (dist_key<<12 | orig_idx). Unique keys -> the 20
// smallest form an order-invariant set, and tie ordering matches jax top_k
// exactly (verified R7-R9). Each candidate position must be inserted EXACTLY
// once (R10/R13 bugs were both double-insertion).
__device__ __forceinline__ void insert20k(unsigned long long k,
                                          unsigned long long (&val)[K_NN]) {
#pragma unroll
    for (int j = 0; j < K_NN; j++) {
        unsigned long long vj = val[j];
        bool lt = k < vj;
        val[j] = lt ? k : vj;     // keep smaller
        k      = lt ? vj : k;     // carry larger
    }
}

// exact reference-rounding distance from scaled point (px2=-2x etc.)
__device__ __forceinline__ float exact_d(float qx, float qy, float qz, float qw,
                                         float4 p) {
    float px = __fmul_rn(-0.5f, p.x);   // exact (power of two scale)
    float py = __fmul_rn(-0.5f, p.y);
    float pz = __fmul_rn(-0.5f, p.z);
    float t = __fadd_rn(__fadd_rn(__fmul_rn(qx, px), __fmul_rn(qy, py)),
                        __fmul_rn(qz, pz));
    return __fsub_rn(__fadd_rn(qw, p.w), __fmul_rn(2.0f, t));
}

// =============================================================================
// Kernel 0: per-batch bitonic sort by x-coordinate (u64 key = xkey<<16 | idx).
// Emits sorted pre-scaled points, sorted->orig and orig->sorted maps.
// =============================================================================
__global__ void __launch_bounds__(512, 1)
sort_kernel(const float* __restrict__ x) {
    __shared__ unsigned long long keys[N_PTS];      // 32 KB
    const int b = blockIdx.x;
    const float* xb = x + (size_t)b * N_PTS * 3;

    for (int i = threadIdx.x; i < N_PTS; i += 512)
        keys[i] = ((unsigned long long)fkey(xb[i * 3]) << 16) | (unsigned)i;
    __syncthreads();

    for (int k = 2; k <= N_PTS; k <<= 1) {
        for (int j = k >> 1; j > 0; j >>= 1) {
            for (int i = threadIdx.x; i < N_PTS; i += 512) {
                int ixj = i ^ j;
                if (ixj > i) {
                    bool up = ((i & k) == 0);
                    unsigned long long a = keys[i], c = keys[ixj];
                    if ((a > c) == up) { keys[i] = c; keys[ixj] = a; }
                }
            }
            __syncthreads();
        }
    }

    for (int i = threadIdx.x; i < N_PTS; i += 512) {
        unsigned orig = (unsigned)(keys[i] & 0xFFFFu);
        float x0 = xb[orig * 3 + 0], x1 = xb[orig * 3 + 1], x2 = xb[orig * 3 + 2];
        float sq = __fadd_rn(__fadd_rn(__fmul_rn(x0, x0), __fmul_rn(x1, x1)),
                             __fmul_rn(x2, x2));
        g_sorted[b * N_PTS + i] = make_float4(
            __fmul_rn(-2.0f, x0), __fmul_rn(-2.0f, x1), __fmul_rn(-2.0f, x2), sq);
        g_oidx[b * N_PTS + i] = (unsigned short)orig;
        g_map[b * N_PTS + orig] = (unsigned short)i;
    }
}

// =============================================================================
// Kernel 1: axis-windowed exact KNN, single linear branch-free scan.
//   Phase A: exact keyed insert of the 64 sorted-nearest [loA,hiA) -> d20_A.
//   Window: xlim = sqrt(d20_A*1.0001+1e-4) bounds every possible final
//     neighbor (sound: |dx|^2 <= exact_d + 6e-6 <= d20_A + 6e-6 < dstop).
//     Binary-search the sorted x array for the window, warp-reduce to a
//     uniform 32-aligned span [gl, gr) (gl aligned & N%32==0 -> no bounds
//     checks in the scan at all).
//   Scan: per candidate = LDS.128 + 3-FFMA screen vs tau + predicated push
//     with the Phase-A exclusion (m-loA) >= 64 folded into the predicate
//     (exact: hiA == loA+64 by construction). Headroom guard once per
//     32-group; flush only when near-full (+ final flush): exact recompute,
//     u64 keyed insert, tau refresh.
// FUSED with fp64 BatchNorm moment accumulation (epilogue).
// =============================================================================
__global__ void __launch_bounds__(512, 1)
knn_stats_kernel() {
    extern __shared__ char smem_raw[];
    float4*         pts = (float4*)smem_raw;                          // 64 KB
    unsigned short* osx = (unsigned short*)(smem_raw + 65536);        // 8 KB
    unsigned short* mp  = (unsigned short*)(smem_raw + 65536 + 8192); // 8 KB
    char*        stacks = smem_raw + 65536 + 16384;                   // 64 KB

    const int b    = blockIdx.y;
    const int qblk = blockIdx.x;

    for (int i = threadIdx.x; i < N_PTS; i += 512) {
        pts[i] = g_sorted[b * N_PTS + i];
        osx[i] = g_oidx[b * N_PTS + i];
        mp[i]  = g_map[b * N_PTS + i];
    }
    __syncthreads();

    const int p = qblk * 512 + threadIdx.x;         // query's sorted position
    const float4 qp = pts[p];
    const float qx = __fmul_rn(-0.5f, qp.x);
    const float qy = __fmul_rn(-0.5f, qp.y);
    const float qz = __fmul_rn(-0.5f, qp.z);
    const float qw = qp.w;
    const float qx2 = qp.x;                          // -2x (a-space center)

    // per-lane stack (shared space), 4B slots, 128B stride
    const unsigned sbase =
        (unsigned)__cvta_generic_to_shared(
            stacks + (size_t)(threadIdx.x >> 5) * (CAP * 128)) +
        (threadIdx.x & 31) * 4;
    const unsigned limit = sbase + CAP * 128;
    unsigned addr = sbase;

    const unsigned pts_s = (unsigned)__cvta_generic_to_shared(pts);

    unsigned long long val[K_NN];
#pragma unroll
    for (int j = 0; j < K_NN; j++) val[j] = 0xFFFFFFFFFFFFFFFFull;

    // ---- Phase A: exact insert over the clamped window [loA, loA+64) ----
    int loA = p - 32; if (loA < 0) loA = 0;
    if (loA + 64 > N_PTS) loA = N_PTS - 64;          // hiA == loA+64 always
#pragma unroll 2
    for (int m = loA; m < loA + 64; m++) {
        float d = exact_d(qx, qy, qz, qw, pts[m]);
        unsigned long long k =
            ((unsigned long long)fkey(d) << 12) | (unsigned)osx[m];
        if (k < val[K_NN - 1]) insert20k(k, val);
    }
    float d20f = fkey_inv((unsigned)(val[K_NN - 1] >> 12));
    float tau = d20f - qw + SLACK;

    // ---- window bounds via binary search on sorted x (a = -2x, DESCENDING) ----
    // |a_i - qx2| <= 2*xlim  <=>  t_lo <= a_i <= t_hi, contiguous since sorted.
    const float xlim = fmaf(sqrtf(fmaf(d20f, 1.0001f, 1e-4f)), 1.0001f, 1e-6f);
    const float t_hi = qx2 + 2.0f * xlim;
    const float t_lo = qx2 - 2.0f * xlim;

    int lo_w;                                        // first i with a_i <= t_hi
    {
        int lo = 0, hi = N_PTS;
        while (lo < hi) {
            int mid = (lo + hi) >> 1;
            if (pts[mid].x <= t_hi) hi = mid; else lo = mid + 1;
        }
        lo_w = lo;
    }
    int hi_w;                                        // first i with a_i < t_lo
    {
        int lo = 0, hi = N_PTS;
        while (lo < hi) {
            int mid = (lo + hi) >> 1;
            if (pts[mid].x < t_lo) hi = mid; else lo = mid + 1;
        }
        hi_w = lo;
    }

    int gl = lo_w, gr = hi_w;
#pragma unroll
    for (int o = 16; o > 0; o >>= 1) {
        gl = min(gl, __shfl_xor_sync(0xFFFFFFFFu, gl, o));
        gr = max(gr, __shfl_xor_sync(0xFFFFFFFFu, gr, o));
    }
    gl &= ~31;                                       // 32-aligned; N%32==0 ->
                                                     // groups never leave [0,N)
    // ---- single linear scan of [gl, gr) in 32-groups ----
#pragma unroll 1
    for (int g = gl; g < gr; g += 32) {
        if (__any_sync(0xFFFFFFFFu, addr + 32u * 128u > limit)) {
            // flush (rare): exact recompute + keyed insert, tau refresh
            const unsigned stop = addr;
            for (unsigned pp = sbase; pp < stop; pp += 128) {
                unsigned m;
                asm volatile("ld.shared.b32 %0, [%1];" : "=r"(m) : "r"(pp));
                float d = exact_d(qx, qy, qz, qw, pts[m]);
                unsigned long long k =
                    ((unsigned long long)fkey(d) << 12) | (unsigned)osx[m];
                if (k < val[K_NN - 1]) insert20k(k, val);
            }
            addr = sbase;
            d20f = fkey_inv((unsigned)(val[K_NN - 1] >> 12));
            tau = d20f - qw + SLACK;
        }
#pragma unroll 8
        for (int mm = 0; mm < 32; mm++) {
            const int m = g + mm;
            const unsigned mdiff = (unsigned)(m - loA);   // >=64 <=> outside Phase A
            float4 pc;
            asm volatile("ld.shared.v4.b32 {%0,%1,%2,%3}, [%4];"
                         : "=f"(pc.x), "=f"(pc.y), "=f"(pc.z), "=f"(pc.w)
                         : "r"(pts_s + m * 16));
            float ds = fmaf(pc.x, qx, fmaf(pc.y, qy, fmaf(pc.z, qz, pc.w)));
            asm volatile(
                "{\n\t"
                ".reg .pred p;\n\t"
                "setp.lt.f32 p, %1, %2;\n\t"
                "setp.ge.and.u32 p, %3, 64, p;\n\t"
                "@p st.shared.b32 [%0], %4;\n\t"
                "@p add.u32 %0, %0, 128;\n\t"
                "}"
                : "+r"(addr)
                : "f"(ds), "f"(tau), "r"(mdiff), "r"(m));
        }
    }
    // ---- final flush ----
    {
        const unsigned stop = addr;
        for (unsigned pp = sbase; pp < stop; pp += 128) {
            unsigned m;
            asm volatile("ld.shared.b32 %0, [%1];" : "=r"(m) : "r"(pp));
            float d = exact_d(qx, qy, qz, qw, pts[m]);
            unsigned long long k =
                ((unsigned long long)fkey(d) << 12) | (unsigned)osx[m];
            if (k < val[K_NN - 1]) insert20k(k, val);
        }
    }

    // ---- write indices (row = ORIGINAL query index) ----
    const unsigned oq = osx[p];
    int* op = g_idx + ((size_t)(b * N_PTS) + oq) * K_NN;
#pragma unroll
    for (int j = 0; j < K_NN; j++) op[j] = (int)(val[j] & 0xFFFu);

    // ================= fused BN moment epilogue =================
    const float qix = qx, qiy = qy, qiz = qz;
    float sj0 = 0, sj1 = 0, sj2 = 0;
    float jj00 = 0, jj01 = 0, jj02 = 0, jj11 = 0, jj12 = 0, jj22 = 0;
    float ij00 = 0, ij01 = 0, ij02 = 0, ij10 = 0, ij11 = 0, ij12 = 0,
          ij20 = 0, ij21 = 0, ij22 = 0;
#pragma unroll
    for (int j = 0; j < K_NN; j++) {
        float4 pj = pts[mp[val[j] & 0xFFFu]];
        float pxx = -0.5f * pj.x, pyy = -0.5f * pj.y, pzz = -0.5f * pj.z;
        sj0 += pxx; sj1 += pyy; sj2 += pzz;
        jj00 = fmaf(pxx, pxx, jj00); jj01 = fmaf(pxx, pyy, jj01);
        jj02 = fmaf(pxx, pzz, jj02); jj11 = fmaf(pyy, pyy, jj11);
        jj12 = fmaf(pyy, pzz, jj12); jj22 = fmaf(pzz, pzz, jj22);
        ij00 = fmaf(qix, pxx, ij00); ij01 = fmaf(qix, pyy, ij01);
        ij02 = fmaf(qix, pzz, ij02); ij10 = fmaf(qiy, pxx, ij10);
        ij11 = fmaf(qiy, pyy, ij11); ij12 = fmaf(qiy, pzz, ij12);
        ij20 = fmaf(qiz, pxx, ij20); ij21 = fmaf(qiz, pyy, ij21);
        ij22 = fmaf(qiz, pzz, ij22);
    }

    double vals[NVALS] = {
        (double)qix, (double)qiy, (double)qiz,
        (double)qix * qix, (double)qix * qiy, (double)qix * qiz,
        (double)qiy * qiy, (double)qiy * qiz, (double)qiz * qiz,
        (double)sj0, (double)sj1, (double)sj2,
        (double)jj00, (double)jj01, (double)jj02,
        (double)jj11, (double)jj12, (double)jj22,
        (double)ij00, (double)ij01, (double)ij02,
        (double)ij10, (double)ij11, (double)ij12,
        (double)ij20, (double)ij21, (double)ij22
    };

    __syncthreads();                       // stacks no longer needed
    double* wsum = (double*)stacks;        // [16][NVALS], aliases stacks
    const int wid = threadIdx.x >> 5;
    const int lid = threadIdx.x & 31;
#pragma unroll
    for (int v = 0; v < NVALS; v++) {
        double s = vals[v];
#pragma unroll
        for (int o = 16; o > 0; o >>= 1) s += __shfl_xor_sync(0xFFFFFFFFu, s, o);
        if (lid == 0) wsum[wid * NVALS + v] = s;
    }
    __syncthreads();
    if (threadIdx.x < NVALS) {
        double s = 0.0;
#pragma unroll
        for (int w = 0; w < 16; w++) s += wsum[w * NVALS + threadIdx.x];
        g_part[(blockIdx.y * gridDim.x + blockIdx.x) * NVALS + threadIdx.x] = s;
    }
}

// =============================================================================
// Kernel 2: finalize BN stats -> per-channel scale/shift (fp64 math).
// =============================================================================
__global__ void __launch_bounds__(864, 1)
finalize_kernel(const float* __restrict__ w1,
                const float* __restrict__ b1,
                const float* __restrict__ gamma,
                const float* __restrict__ beta) {
    __shared__ double S[NVALS];
    const int wid = threadIdx.x >> 5;
    const int lid = threadIdx.x & 31;
    if (wid < NVALS) {
        double s = 0.0;
#pragma unroll
        for (int r = 0; r < KNN_BLOCKS / 32; r++)
            s += g_part[(r * 32 + lid) * NVALS + wid];
#pragma unroll
        for (int o = 16; o > 0; o >>= 1) s += __shfl_xor_sync(0xFFFFFFFFu, s, o);
        if (lid == 0) S[wid] = s;
    }
    __syncthreads();
    if (threadIdx.x >= CO) return;

    const int c = threadIdx.x;
    const double M = (double)B_SZ * N_PTS * K_NN;
    const double Kd = (double)K_NN;

    double q0 = (double)w1[3 * CO + c], q1 = (double)w1[4 * CO + c], q2 = (double)w1[5 * CO + c];
    double p0 = (double)w1[0 * CO + c] - q0;
    double p1 = (double)w1[1 * CO + c] - q1;
    double p2 = (double)w1[2 * CO + c] - q2;
    double s_ = (double)b1[c];

    double Si0 = Kd * S[0], Si1 = Kd * S[1], Si2 = Kd * S[2];
    double i00 = Kd * S[3], i01 = Kd * S[4], i02 = Kd * S[5];
    double i11 = Kd * S[6], i12 = Kd * S[7], i22 = Kd * S[8];
    double Sj0 = S[9], Sj1 = S[10], Sj2 = S[11];
    double j00 = S[12], j01 = S[13], j02 = S[14], j11 = S[15], j12 = S[16], j22 = S[17];

    double pSi = p0 * Si0 + p1 * Si1 + p2 * Si2;
    double qSj = q0 * Sj0 + q1 * Sj1 + q2 * Sj2;
    double mean = (pSi + qSj) / M + s_;

    double pMp = p0 * p0 * i00 + p1 * p1 * i11 + p2 * p2 * i22 +
                 2.0 * (p0 * p1 * i01 + p0 * p2 * i02 + p1 * p2 * i12);
    double qMq = q0 * q0 * j00 + q1 * q1 * j11 + q2 * q2 * j22 +
                 2.0 * (q0 * q1 * j01 + q0 * q2 * j02 + q1 * q2 * j12);
    double pMq = p0 * (q0 * S[18] + q1 * S[19] + q2 * S[20]) +
                 p1 * (q0 * S[21] + q1 * S[22] + q2 * S[23]) +
                 p2 * (q0 * S[24] + q1 * S[25] + q2 * S[26]);

    double sumsq = pMp + qMq + 2.0 * pMq + 2.0 * s_ * (pSi + qSj) + M * s_ * s_;
    double var = sumsq / M - mean * mean;
    double rstd = 1.0 / sqrt(var + 1e-5);

    double g = (double)gamma[c];
    g_scale[c] = (float)(g * rstd);
    g_shift[c] = (float)((double)beta[c] - mean * g * rstd);
}

// =============================================================================
// Kernel 3: fused edge-MLP + BN + ReLU + (r @ w2) + max over K.
// One warp per point, 2 channels/lane. At the FFMA2 structural roofline.
// =============================================================================
__global__ void __launch_bounds__(256, 3)
main_kernel(const float* __restrict__ x,
            const float* __restrict__ w1,
            const float* __restrict__ b1,
            const float* __restrict__ w2,
            const float* __restrict__ b2,
            float* __restrict__ out) {
    extern __shared__ float sm[];
    float2* w2p = (float2*)sm;             // [64][32] float2
    float*  rt  = sm + CO * CO;            // 8 warps * 64 * 20

    for (int i = threadIdx.x; i < CO * 32; i += blockDim.x) {
        int c = i >> 5, l = i & 31;
        w2p[i] = make_float2(w2[c * CO + l], w2[c * CO + l + 32]);
    }
    __syncthreads();

    const int w = threadIdx.x >> 5;
    const int l = threadIdx.x & 31;
    const int pt = blockIdx.x * 8 + w;
    float* rw = rt + w * (CO * K_NN);

    const int ca = l, cb = l + 32;

    float wja[3], wjb[3], wia[3], wib[3];
#pragma unroll
    for (int r = 0; r < 3; r++) {
        float a0 = __ldg(w1 + r * CO + ca);
        float a3 = __ldg(w1 + (r + 3) * CO + ca);
        float b0 = __ldg(w1 + r * CO + cb);
        float b3 = __ldg(w1 + (r + 3) * CO + cb);
        wja[r] = a3; wjb[r] = b3;
        wia[r] = a0 - a3; wib[r] = b0 - b3;
    }
    const float b1a = __ldg(b1 + ca), b1b = __ldg(b1 + cb);
    const float sca = g_scale[ca], scb = g_scale[cb];
    const float sha = g_shift[ca], shb = g_shift[cb];

    const int b = pt >> 12;
    const int gbase = b << 12;
    const float* xr = x + (size_t)pt * 3;
    const float xi0 = __ldg(xr), xi1 = __ldg(xr + 1), xi2 = __ldg(xr + 2);
    const int* ip = g_idx + (size_t)pt * K_NN;

    const float basea = fmaf(xi2, wia[2], fmaf(xi1, wia[1], fmaf(xi0, wia[0], b1a)));
    const float baseb = fmaf(xi2, wib[2], fmaf(xi1, wib[1], fmaf(xi0, wib[0], b1b)));

    // ---- stage 1: r[c][k] = relu(scale*h + shift) ----
#pragma unroll 4
    for (int k = 0; k < K_NN; k++) {
        int j = __ldg(ip + k);
        const float* xp = x + (size_t)(gbase + j) * 3;
        float j0 = __ldg(xp), j1 = __ldg(xp + 1), j2 = __ldg(xp + 2);

        float ha = fmaf(j2, wja[2], fmaf(j1, wja[1], fmaf(j0, wja[0], basea)));
        float hb = fmaf(j2, wjb[2], fmaf(j1, wjb[1], fmaf(j0, wjb[0], baseb)));

        rw[ca * K_NN + k] = fmaxf(fmaf(ha, sca, sha), 0.0f);
        rw[cb * K_NN + k] = fmaxf(fmaf(hb, scb, shb), 0.0f);
    }
    __syncwarp();

    // ---- stage 2: packed FFMA2 GEMM, acc[i] holds k=(2i, 2i+1) ----
    unsigned long long acca[K_NN / 2], accb[K_NN / 2];
#pragma unroll
    for (int i = 0; i < K_NN / 2; i++) { acca[i] = 0ULL; accb[i] = 0ULL; }

#pragma unroll 4
    for (int c = 0; c < CO; c++) {
        float2 wab = w2p[c * 32 + l];
        unsigned long long wa2 = pack2(wab.x, wab.x);
        unsigned long long wb2 = pack2(wab.y, wab.y);
        const ulonglong2* r2 = (const ulonglong2*)(rw + c * K_NN);
#pragma unroll
        for (int t = 0; t < 5; t++) {
            ulonglong2 rv = r2[t];
            FMA2(acca[2 * t],     rv.x, wa2, acca[2 * t]);
            FMA2(acca[2 * t + 1], rv.y, wa2, acca[2 * t + 1]);
            FMA2(accb[2 * t],     rv.x, wb2, accb[2 * t]);
            FMA2(accb[2 * t + 1], rv.y, wb2, accb[2 * t + 1]);
        }
    }

    float ma = -3.402823466e38f, mb = -3.402823466e38f;
#pragma unroll
    for (int i = 0; i < K_NN / 2; i++) {
        float a0, a1, b0, b1v;
        unpack2(acca[i], a0, a1);
        unpack2(accb[i], b0, b1v);
        ma = fmaxf(ma, fmaxf(a0, a1));
        mb = fmaxf(mb, fmaxf(b0, b1v));
    }

    out[(size_t)pt * CO + ca] = ma + __ldg(b2 + ca);
    out[(size_t)pt * CO + cb] = mb + __ldg(b2 + cb);
}

// =============================================================================
extern "C" void kernel_launch(void* const* d_in, const int* in_sizes, int n_in,
                              void* d_out, int out_size) {
    const float* x     = (const float*)d_in[0];
    // d_in[1] = batch indices (implied by layout; unused)
    const float* w1    = (const float*)d_in[2];
    const float* b1    = (const float*)d_in[3];
    const float* gamma = (const float*)d_in[4];
    const float* beta  = (const float*)d_in[5];
    const float* w2    = (const float*)d_in[6];
    const float* b2    = (const float*)d_in[7];
    float* out = (float*)d_out;

    const int knn_smem  = 65536 + 16384 + 16 * CAP * 128;               // 146 KB
    const int main_smem = (CO * CO + 8 * CO * K_NN) * sizeof(float);    // 56 KB

    cudaFuncSetAttribute(knn_stats_kernel, cudaFuncAttributeMaxDynamicSharedMemorySize, knn_smem);
    cudaFuncSetAttribute(main_kernel,      cudaFuncAttributeMaxDynamicSharedMemorySize, main_smem);

    sort_kernel<<<B_SZ, 512>>>(x);
    knn_stats_kernel<<<dim3(8, B_SZ), 512, knn_smem>>>();
    finalize_kernel<<<1, 864>>>(w1, b1, gamma, beta);
    main_kernel<<<(B_SZ * N_PTS) / 8, 256, main_smem>>>(x, w1, b1, w2, b2, out);
}

// round 16
// speedup vs baseline: 1.1436x; 1.1436x over previous
#include <cuda_runtime.h>
#include <math_constants.h>

#define B_SZ 16
#define N_PTS 4096
#define K_NN 20
#define CO 64
#define KNN_BLOCKS 128
#define NVALS 27
#define CAP 32          // per-lane smem stack capacity (4B slots)
#define SLAB 512
#define SLACK 2e-3f

// ---------------- scratch (static device allocations, allowed) ----------------
__device__ int            g_idx[B_SZ * N_PTS * K_NN];     // 5.24 MB
__device__ float4         g_sorted[B_SZ * N_PTS];         // 4 MB  (sorted by x)
__device__ unsigned short g_oidx[B_SZ * N_PTS];           // sorted pos -> orig idx
__device__ unsigned short g_map[B_SZ * N_PTS];            // orig idx  -> sorted pos
__device__ double         g_part[KNN_BLOCKS * NVALS];
__device__ float          g_scale[CO];
__device__ float          g_shift[CO];

// packed f32x2 helpers (sm_100+ PTX)
__device__ __forceinline__ unsigned long long pack2(float lo, float hi) {
    unsigned long long r;
    asm("mov.b64 %0, {%1,%2};" : "=l"(r) : "f"(lo), "f"(hi));
    return r;
}
__device__ __forceinline__ void unpack2(unsigned long long v, float& lo, float& hi) {
    asm("mov.b64 {%0,%1}, %2;" : "=f"(lo), "=f"(hi) : "l"(v));
}
#define FMA2(d, a, b, c) \
    asm("fma.rn.f32x2 %0, %1, %2, %3;" : "=l"(d) : "l"(a), "l"(b), "l"(c))

// float bits -> order-preserving u32 key (handles negatives)
__device__ __forceinline__ unsigned fkey(float f) {
    unsigned b = __float_as_uint(f);
    return b ^ ((unsigned)((int)b >> 31) | 0x80000000u);
}
__device__ __forceinline__ float fkey_inv(unsigned t) {
    unsigned b = (t & 0x80000000u) ? (t ^ 0x80000000u) : ~t;
    return __uint_as_float(b);
}

// sorted top-20 as u64 keys (dist_key<<12 | orig_idx). Unique keys -> the 20
// smallest form an order-invariant set, and tie ordering matches jax top_k
// exactly (verified R7-R9). Each candidate position must be inserted EXACTLY
// once (R10/R13 bugs were both double-insertion).
__device__ __forceinline__ void insert20k(unsigned long long k,
                                          unsigned long long (&val)[K_NN]) {
#pragma unroll
    for (int j = 0; j < K_NN; j++) {
        unsigned long long vj = val[j];
        bool lt = k < vj;
        val[j] = lt ? k : vj;     // keep smaller
        k      = lt ? vj : k;     // carry larger
    }
}

// exact reference-rounding distance from scaled point (px2=-2x etc.)
__device__ __forceinline__ float exact_d(float qx, float qy, float qz, float qw,
                                         float4 p) {
    float px = __fmul_rn(-0.5f, p.x);   // exact (power of two scale)
    float py = __fmul_rn(-0.5f, p.y);
    float pz = __fmul_rn(-0.5f, p.z);
    float t = __fadd_rn(__fadd_rn(__fmul_rn(qx, px), __fmul_rn(qy, py)),
                        __fmul_rn(qz, pz));
    return __fsub_rn(__fadd_rn(qw, p.w), __fmul_rn(2.0f, t));
}

// =============================================================================
// Kernel 0: per-batch bitonic sort by x-coordinate (u64 key = xkey<<16 | idx).
// =============================================================================
__global__ void __launch_bounds__(512, 1)
sort_kernel(const float* __restrict__ x) {
    __shared__ unsigned long long keys[N_PTS];      // 32 KB
    const int b = blockIdx.x;
    const float* xb = x + (size_t)b * N_PTS * 3;

    for (int i = threadIdx.x; i < N_PTS; i += 512)
        keys[i] = ((unsigned long long)fkey(xb[i * 3]) << 16) | (unsigned)i;
    __syncthreads();

    for (int k = 2; k <= N_PTS; k <<= 1) {
        for (int j = k >> 1; j > 0; j >>= 1) {
            for (int i = threadIdx.x; i < N_PTS; i += 512) {
                int ixj = i ^ j;
                if (ixj > i) {
                    bool up = ((i & k) == 0);
                    unsigned long long a = keys[i], c = keys[ixj];
                    if ((a > c) == up) { keys[i] = c; keys[ixj] = a; }
                }
            }
            __syncthreads();
        }
    }

    for (int i = threadIdx.x; i < N_PTS; i += 512) {
        unsigned orig = (unsigned)(keys[i] & 0xFFFFu);
        float x0 = xb[orig * 3 + 0], x1 = xb[orig * 3 + 1], x2 = xb[orig * 3 + 2];
        float sq = __fadd_rn(__fadd_rn(__fmul_rn(x0, x0), __fmul_rn(x1, x1)),
                             __fmul_rn(x2, x2));
        g_sorted[b * N_PTS + i] = make_float4(
            __fmul_rn(-2.0f, x0), __fmul_rn(-2.0f, x1),
            __fmul_rn(-2.0f, x2), sq);
        g_oidx[b * N_PTS + i] = (unsigned short)orig;
        g_map[b * N_PTS + orig] = (unsigned short)i;
    }
}

// =============================================================================
// Kernel 1: axis-windowed exact KNN with tau-tightening slab prepass.
//   Phase A: exact keyed insert over the 64 sorted-nearest [loA, loA+64).
//   Phase B: branch-free slab scan of SLAB=512 sorted-neighbors [loS,loS+512)
//     (contains Phase A; excluded via (m-loA)>=64 predicate). This tightens
//     d20 to ~40/512 BEFORE the window is computed (R15 failure: window from
//     the 64-point d20 ~ 40/64 covered most of the array).
//   Window: xlim = (sqrt(d20*1.0001+1e-4))*1.0001+1e-6 bounds every possible
//     final neighbor (sound: dx^2 <= exact_d + 6e-6 <= d20 + 6e-6 < xlim^2).
//     Binary-search sorted x (a=-2x DESCENDING), warp-reduce to uniform span.
//   Span scan: [gl,gr) excluding the per-lane slab via (m-loS)>=512 predicate
//     (+ m<gr bound; OOB loads clamped). Coverage across the three phases is
//     exactly-once per position.
//   All screening: LDS.128 + 3-FFMA vs tau + predicated push; headroom guard
//   once per 32-group; flush = exact recompute + u64 keyed insert + tau
//   refresh. FUSED with fp64 BN moment accumulation (epilogue).
// =============================================================================
__global__ void __launch_bounds__(512, 1)
knn_stats_kernel() {
    extern __shared__ char smem_raw[];
    float4*         pts = (float4*)smem_raw;                          // 64 KB
    unsigned short* osx = (unsigned short*)(smem_raw + 65536);        // 8 KB
    unsigned short* mp  = (unsigned short*)(smem_raw + 65536 + 8192); // 8 KB
    char*        stacks = smem_raw + 65536 + 16384;                   // 64 KB

    const int b    = blockIdx.y;
    const int qblk = blockIdx.x;

    for (int i = threadIdx.x; i < N_PTS; i += 512) {
        pts[i] = g_sorted[b * N_PTS + i];
        osx[i] = g_oidx[b * N_PTS + i];
        mp[i]  = g_map[b * N_PTS + i];
    }
    __syncthreads();

    const int p = qblk * 512 + threadIdx.x;         // query's sorted position
    const float4 qp = pts[p];
    const float qx = __fmul_rn(-0.5f, qp.x);
    const float qy = __fmul_rn(-0.5f, qp.y);
    const float qz = __fmul_rn(-0.5f, qp.z);
    const float qw = qp.w;
    const float qx2 = qp.x;                          // -2x (a-space center)

    // per-lane stack (shared space), 4B slots, 128B stride
    const unsigned sbase =
        (unsigned)__cvta_generic_to_shared(
            stacks + (size_t)(threadIdx.x >> 5) * (CAP * 128)) +
        (threadIdx.x & 31) * 4;
    const unsigned limit = sbase + CAP * 128;
    unsigned addr = sbase;

    const unsigned pts_s = (unsigned)__cvta_generic_to_shared(pts);

    unsigned long long val[K_NN];
#pragma unroll
    for (int j = 0; j < K_NN; j++) val[j] = 0xFFFFFFFFFFFFFFFFull;

    // ---- Phase A: exact insert over the clamped window [loA, loA+64) ----
    int loA = p - 32; if (loA < 0) loA = 0;
    if (loA + 64 > N_PTS) loA = N_PTS - 64;          // hiA == loA+64 always
#pragma unroll 2
    for (int m = loA; m < loA + 64; m++) {
        float d = exact_d(qx, qy, qz, qw, pts[m]);
        unsigned long long k =
            ((unsigned long long)fkey(d) << 12) | (unsigned)osx[m];
        if (k < val[K_NN - 1]) insert20k(k, val);
    }
    float d20f = fkey_inv((unsigned)(val[K_NN - 1] >> 12));
    float tau = d20f - qw + SLACK;

#define FLUSH_STACK() do {                                                    \
    const unsigned _stop = addr;                                              \
    for (unsigned _pp = sbase; _pp < _stop; _pp += 128) {                     \
        unsigned _m;                                                          \
        asm volatile("ld.shared.b32 %0, [%1];" : "=r"(_m) : "r"(_pp));        \
        float _d = exact_d(qx, qy, qz, qw, pts[_m]);                          \
        unsigned long long _k =                                               \
            ((unsigned long long)fkey(_d) << 12) | (unsigned)osx[_m];         \
        if (_k < val[K_NN - 1]) insert20k(_k, val);                           \
    }                                                                         \
    addr = sbase;                                                             \
    d20f = fkey_inv((unsigned)(val[K_NN - 1] >> 12));                         \
    tau = d20f - qw + SLACK;                                                  \
} while (0)

    // ---- Phase B: slab scan [loS, loS+SLAB), excluding Phase A ----
    int loS = loA - 224;
    if (loS < 0) loS = 0;
    if (loS > N_PTS - SLAB) loS = N_PTS - SLAB;      // Phase A always inside

#pragma unroll 1
    for (int g = 0; g < SLAB; g += 32) {
        if (__any_sync(0xFFFFFFFFu, addr + 32u * 128u > limit)) FLUSH_STACK();
#pragma unroll 8
        for (int mm = 0; mm < 32; mm++) {
            const int m = loS + g + mm;
            const unsigned mdA = (unsigned)(m - loA);     // >=64 <=> outside A
            float4 pc;
            asm volatile("ld.shared.v4.b32 {%0,%1,%2,%3}, [%4];"
                         : "=f"(pc.x), "=f"(pc.y), "=f"(pc.z), "=f"(pc.w)
                         : "r"(pts_s + m * 16));
            float ds = fmaf(pc.x, qx, fmaf(pc.y, qy, fmaf(pc.z, qz, pc.w)));
            asm volatile(
                "{\n\t"
                ".reg .pred p;\n\t"
                "setp.lt.f32 p, %1, %2;\n\t"
                "setp.ge.and.u32 p, %3, 64, p;\n\t"
                "@p st.shared.b32 [%0], %4;\n\t"
                "@p add.u32 %0, %0, 128;\n\t"
                "}"
                : "+r"(addr)
                : "f"(ds), "f"(tau), "r"(mdA), "r"(m));
        }
    }
    FLUSH_STACK();                                   // tau now tight (~40/512)

    // ---- window bounds via binary search on sorted x (a=-2x, DESCENDING) ----
    const float xlim = fmaf(sqrtf(fmaf(d20f, 1.0001f, 1e-4f)), 1.0001f, 1e-6f);
    const float t_hi = qx2 + 2.0f * xlim;
    const float t_lo = qx2 - 2.0f * xlim;

    int lo_w;                                        // first i with a_i <= t_hi
    {
        int lo = 0, hi = N_PTS;
        while (lo < hi) {
            int mid = (lo + hi) >> 1;
            if (pts[mid].x <= t_hi) hi = mid; else lo = mid + 1;
        }
        lo_w = lo;
    }
    int hi_w;                                        // first i with a_i < t_lo
    {
        int lo = 0, hi = N_PTS;
        while (lo < hi) {
            int mid = (lo + hi) >> 1;
            if (pts[mid].x < t_lo) hi = mid; else lo = mid + 1;
        }
        hi_w = lo;
    }

    int gl = lo_w, gr = hi_w;
#pragma unroll
    for (int o = 16; o > 0; o >>= 1) {
        gl = min(gl, __shfl_xor_sync(0xFFFFFFFFu, gl, o));
        gr = max(gr, __shfl_xor_sync(0xFFFFFFFFu, gr, o));
    }

    // ---- span scan [gl, gr), excluding per-lane slab [loS, loS+SLAB) ----
#pragma unroll 1
    for (int g = gl; g < gr; g += 32) {
        if (__any_sync(0xFFFFFFFFu, addr + 32u * 128u > limit)) FLUSH_STACK();
#pragma unroll 8
        for (int mm = 0; mm < 32; mm++) {
            const int m = g + mm;
            const int mc = m < N_PTS ? m : N_PTS - 1;     // safe spec. load
            const unsigned mdS = (unsigned)(m - loS);     // >=SLAB <=> outside
            float4 pc;
            asm volatile("ld.shared.v4.b32 {%0,%1,%2,%3}, [%4];"
                         : "=f"(pc.x), "=f"(pc.y), "=f"(pc.z), "=f"(pc.w)
                         : "r"(pts_s + mc * 16));
            float ds = fmaf(pc.x, qx, fmaf(pc.y, qy, fmaf(pc.z, qz, pc.w)));
            asm volatile(
                "{\n\t"
                ".reg .pred p;\n\t"
                "setp.lt.f32 p, %1, %2;\n\t"
                "setp.ge.and.u32 p, %3, %4, p;\n\t"
                "setp.lt.and.s32 p, %5, %6, p;\n\t"
                "@p st.shared.b32 [%0], %5;\n\t"
                "@p add.u32 %0, %0, 128;\n\t"
                "}"
                : "+r"(addr)
                : "f"(ds), "f"(tau), "r"(mdS), "r"((unsigned)SLAB),
                  "r"(m), "r"(gr));
        }
    }
    FLUSH_STACK();
#undef FLUSH_STACK

    // ---- write indices (row = ORIGINAL query index) ----
    const unsigned oq = osx[p];
    int* op = g_idx + ((size_t)(b * N_PTS) + oq) * K_NN;
#pragma unroll
    for (int j = 0; j < K_NN; j++) op[j] = (int)(val[j] & 0xFFFu);

    // ================= fused BN moment epilogue =================
    const float qix = qx, qiy = qy, qiz = qz;
    float sj0 = 0, sj1 = 0, sj2 = 0;
    float jj00 = 0, jj01 = 0, jj02 = 0, jj11 = 0, jj12 = 0, jj22 = 0;
    float ij00 = 0, ij01 = 0, ij02 = 0, ij10 = 0, ij11 = 0, ij12 = 0,
          ij20 = 0, ij21 = 0, ij22 = 0;
#pragma unroll
    for (int j = 0; j < K_NN; j++) {
        float4 pj = pts[mp[val[j] & 0xFFFu]];
        float pxx = -0.5f * pj.x, pyy = -0.5f * pj.y, pzz = -0.5f * pj.z;
        sj0 += pxx; sj1 += pyy; sj2 += pzz;
        jj00 = fmaf(pxx, pxx, jj00); jj01 = fmaf(pxx, pyy, jj01);
        jj02 = fmaf(pxx, pzz, jj02); jj11 = fmaf(pyy, pyy, jj11);
        jj12 = fmaf(pyy, pzz, jj12); jj22 = fmaf(pzz, pzz, jj22);
        ij00 = fmaf(qix, pxx, ij00); ij01 = fmaf(qix, pyy, ij01);
        ij02 = fmaf(qix, pzz, ij02); ij10 = fmaf(qiy, pxx, ij10);
        ij11 = fmaf(qiy, pyy, ij11); ij12 = fmaf(qiy, pzz, ij12);
        ij20 = fmaf(qiz, pxx, ij20); ij21 = fmaf(qiz, pyy, ij21);
        ij22 = fmaf(qiz, pzz, ij22);
    }

    double vals[NVALS] = {
        (double)qix, (double)qiy, (double)qiz,
        (double)qix * qix, (double)qix * qiy, (double)qix * qiz,
        (double)qiy * qiy, (double)qiy * qiz, (double)qiz * qiz,
        (double)sj0, (double)sj1, (double)sj2,
        (double)jj00, (double)jj01, (double)jj02,
        (double)jj11, (double)jj12, (double)jj22,
        (double)ij00, (double)ij01, (double)ij02,
        (double)ij10, (double)ij11, (double)ij12,
        (double)ij20, (double)ij21, (double)ij22
    };

    __syncthreads();                       // stacks no longer needed
    double* wsum = (double*)stacks;        // [16][NVALS], aliases stacks
    const int wid = threadIdx.x >> 5;
    const int lid = threadIdx.x & 31;
#pragma unroll
    for (int v = 0; v < NVALS; v++) {
        double s = vals[v];
#pragma unroll
        for (int o = 16; o > 0; o >>= 1) s += __shfl_xor_sync(0xFFFFFFFFu, s, o);
        if (lid == 0) wsum[wid * NVALS + v] = s;
    }
    __syncthreads();
    if (threadIdx.x < NVALS) {
        double s = 0.0;
#pragma unroll
        for (int w = 0; w < 16; w++) s += wsum[w * NVALS + threadIdx.x];
        g_part[(blockIdx.y * gridDim.x + blockIdx.x) * NVALS + threadIdx.x] = s;
    }
}

// =============================================================================
// Kernel 2: finalize BN stats -> per-channel scale/shift (fp64 math).
// =============================================================================
__global__ void __launch_bounds__(864, 1)
finalize_kernel(const float* __restrict__ w1,
                const float* __restrict__ b1,
                const float* __restrict__ gamma,
                const float* __restrict__ beta) {
    __shared__ double S[NVALS];
    const int wid = threadIdx.x >> 5;
    const int lid = threadIdx.x & 31;
    if (wid < NVALS) {
        double s = 0.0;
#pragma unroll
        for (int r = 0; r < KNN_BLOCKS / 32; r++)
            s += g_part[(r * 32 + lid) * NVALS + wid];
#pragma unroll
        for (int o = 16; o > 0; o >>= 1) s += __shfl_xor_sync(0xFFFFFFFFu, s, o);
        if (lid == 0) S[wid] = s;
    }
    __syncthreads();
    if (threadIdx.x >= CO) return;

    const int c = threadIdx.x;
    const double M = (double)B_SZ * N_PTS * K_NN;
    const double Kd = (double)K_NN;

    double q0 = (double)w1[3 * CO + c], q1 = (double)w1[4 * CO + c], q2 = (double)w1[5 * CO + c];
    double p0 = (double)w1[0 * CO + c] - q0;
    double p1 = (double)w1[1 * CO + c] - q1;
    double p2 = (double)w1[2 * CO + c] - q2;
    double s_ = (double)b1[c];

    double Si0 = Kd * S[0], Si1 = Kd * S[1], Si2 = Kd * S[2];
    double i00 = Kd * S[3], i01 = Kd * S[4], i02 = Kd * S[5];
    double i11 = Kd * S[6], i12 = Kd * S[7], i22 = Kd * S[8];
    double Sj0 = S[9], Sj1 = S[10], Sj2 = S[11];
    double j00 = S[12], j01 = S[13], j02 = S[14], j11 = S[15], j12 = S[16], j22 = S[17];

    double pSi = p0 * Si0 + p1 * Si1 + p2 * Si2;
    double qSj = q0 * Sj0 + q1 * Sj1 + q2 * Sj2;
    double mean = (pSi + qSj) / M + s_;

    double pMp = p0 * p0 * i00 + p1 * p1 * i11 + p2 * p2 * i22 +
                 2.0 * (p0 * p1 * i01 + p0 * p2 * i02 + p1 * p2 * i12);
    double qMq = q0 * q0 * j00 + q1 * q1 * j11 + q2 * q2 * j22 +
                 2.0 * (q0 * q1 * j01 + q0 * q2 * j02 + q1 * q2 * j12);
    double pMq = p0 * (q0 * S[18] + q1 * S[19] + q2 * S[20]) +
                 p1 * (q0 * S[21] + q1 * S[22] + q2 * S[23]) +
                 p2 * (q0 * S[24] + q1 * S[25] + q2 * S[26]);

    double sumsq = pMp + qMq + 2.0 * pMq + 2.0 * s_ * (pSi + qSj) + M * s_ * s_;
    double var = sumsq / M - mean * mean;
    double rstd = 1.0 / sqrt(var + 1e-5);

    double g = (double)gamma[c];
    g_scale[c] = (float)(g * rstd);
    g_shift[c] = (float)((double)beta[c] - mean * g * rstd);
}

// =============================================================================
// Kernel 3: fused edge-MLP + BN + ReLU + (r @ w2) + max over K.
// One warp per point, 2 channels/lane. At the FFMA2 structural roofline.
// =============================================================================
__global__ void __launch_bounds__(256, 3)
main_kernel(const float* __restrict__ x,
            const float* __restrict__ w1,
            const float* __restrict__ b1,
            const float* __restrict__ w2,
            const float* __restrict__ b2,
            float* __restrict__ out) {
    extern __shared__ float sm[];
    float2* w2p = (float2*)sm;             // [64][32] float2
    float*  rt  = sm + CO * CO;            // 8 warps * 64 * 20

    for (int i = threadIdx.x; i < CO * 32; i += blockDim.x) {
        int c = i >> 5, l = i & 31;
        w2p[i] = make_float2(w2[c * CO + l], w2[c * CO + l + 32]);
    }
    __syncthreads();

    const int w = threadIdx.x >> 5;
    const int l = threadIdx.x & 31;
    const int pt = blockIdx.x * 8 + w;
    float* rw = rt + w * (CO * K_NN);

    const int ca = l, cb = l + 32;

    float wja[3], wjb[3], wia[3], wib[3];
#pragma unroll
    for (int r = 0; r < 3; r++) {
        float a0 = __ldg(w1 + r * CO + ca);
        float a3 = __ldg(w1 + (r + 3) * CO + ca);
        float b0 = __ldg(w1 + r * CO + cb);
        float b3 = __ldg(w1 + (r + 3) * CO + cb);
        wja[r] = a3; wjb[r] = b3;
        wia[r] = a0 - a3; wib[r] = b0 - b3;
    }
    const float b1a = __ldg(b1 + ca), b1b = __ldg(b1 + cb);
    const float sca = g_scale[ca], scb = g_scale[cb];
    const float sha = g_shift[ca], shb = g_shift[cb];

    const int b = pt >> 12;
    const int gbase = b << 12;
    const float* xr = x + (size_t)pt * 3;
    const float xi0 = __ldg(xr), xi1 = __ldg(xr + 1), xi2 = __ldg(xr + 2);
    const int* ip = g_idx + (size_t)pt * K_NN;

    const float basea = fmaf(xi2, wia[2], fmaf(xi1, wia[1], fmaf(xi0, wia[0], b1a)));
    const float baseb = fmaf(xi2, wib[2], fmaf(xi1, wib[1], fmaf(xi0, wib[0], b1b)));

    // ---- stage 1: r[c][k] = relu(scale*h + shift) ----
#pragma unroll 4
    for (int k = 0; k < K_NN; k++) {
        int j = __ldg(ip + k);
        const float* xp = x + (size_t)(gbase + j) * 3;
        float j0 = __ldg(xp), j1 = __ldg(xp + 1), j2 = __ldg(xp + 2);

        float ha = fmaf(j2, wja[2], fmaf(j1, wja[1], fmaf(j0, wja[0], basea)));
        float hb = fmaf(j2, wjb[2], fmaf(j1, wjb[1], fmaf(j0, wjb[0], baseb)));

        rw[ca * K_NN + k] = fmaxf(fmaf(ha, sca, sha), 0.0f);
        rw[cb * K_NN + k] = fmaxf(fmaf(hb, scb, shb), 0.0f);
    }
    __syncwarp();

    // ---- stage 2: packed FFMA2 GEMM, acc[i] holds k=(2i, 2i+1) ----
    unsigned long long acca[K_NN / 2], accb[K_NN / 2];
#pragma unroll
    for (int i = 0; i < K_NN / 2; i++) { acca[i] = 0ULL; accb[i] = 0ULL; }

#pragma unroll 4
    for (int c = 0; c < CO; c++) {
        float2 wab = w2p[c * 32 + l];
        unsigned long long wa2 = pack2(wab.x, wab.x);
        unsigned long long wb2 = pack2(wab.y, wab.y);
        const ulonglong2* r2 = (const ulonglong2*)(rw + c * K_NN);
#pragma unroll
        for (int t = 0; t < 5; t++) {
            ulonglong2 rv = r2[t];
            FMA2(acca[2 * t],     rv.x, wa2, acca[2 * t]);
            FMA2(acca[2 * t + 1], rv.y, wa2, acca[2 * t + 1]);
            FMA2(accb[2 * t],     rv.x, wb2, accb[2 * t]);
            FMA2(accb[2 * t + 1], rv.y, wb2, accb[2 * t + 1]);
        }
    }

    float ma = -3.402823466e38f, mb = -3.402823466e38f;
#pragma unroll
    for (int i = 0; i < K_NN / 2; i++) {
        float a0, a1, b0, b1v;
        unpack2(acca[i], a0, a1);
        unpack2(accb[i], b0, b1v);
        ma = fmaxf(ma, fmaxf(a0, a1));
        mb = fmaxf(mb, fmaxf(b0, b1v));
    }

    out[(size_t)pt * CO + ca] = ma + __ldg(b2 + ca);
    out[(size_t)pt * CO + cb] = mb + __ldg(b2 + cb);
}

// =============================================================================
extern "C" void kernel_launch(void* const* d_in, const int* in_sizes, int n_in,
                              void* d_out, int out_size) {
    const float* x     = (const float*)d_in[0];
    // d_in[1] = batch indices (implied by layout; unused)
    const float* w1    = (const float*)d_in[2];
    const float* b1    = (const float*)d_in[3];
    const float* gamma = (const float*)d_in[4];
    const float* beta  = (const float*)d_in[5];
    const float* w2    = (const float*)d_in[6];
    const float* b2    = (const float*)d_in[7];
    float* out = (float*)d_out;

    const int knn_smem  = 65536 + 16384 + 16 * CAP * 128;               // 146 KB
    const int main_smem = (CO * CO + 8 * CO * K_NN) * sizeof(float);    // 56 KB

    cudaFuncSetAttribute(knn_stats_kernel, cudaFuncAttributeMaxDynamicSharedMemorySize, knn_smem);
    cudaFuncSetAttribute(main_kernel,      cudaFuncAttributeMaxDynamicSharedMemorySize, main_smem);

    sort_kernel<<<B_SZ, 512>>>(x);
    knn_stats_kernel<<<dim3(8, B_SZ), 512, knn_smem>>>();
    finalize_kernel<<<1, 864>>>(w1, b1, gamma, beta);
    main_kernel<<<(B_SZ * N_PTS) / 8, 256, main_smem>>>(x, w1, b1, w2, b2, out);
}

// round 17
// speedup vs baseline: 1.2516x; 1.0945x over previous
#include <cuda_runtime.h>

#define B_SZ 16
#define N_PTS 4096
#define K_NN 20
#define CO 64
#define KNN_BLOCKS 128
#define NVALS 27
#define CAP_S 16        // slots per substack (4 substacks/lane); guard => no overflow
#define NCHUNK 14
#define SLACK 2e-3f

// ---------------- scratch (static device allocations, allowed) ----------------
__device__ int    g_idx[B_SZ * N_PTS * K_NN];       // 5.24 MB
__device__ double g_part[KNN_BLOCKS * NVALS];
__device__ float  g_scale[CO];
__device__ float  g_shift[CO];

// packed f32x2 helpers (sm_100+ PTX)
__device__ __forceinline__ unsigned long long pack2(float lo, float hi) {
    unsigned long long r;
    asm("mov.b64 %0, {%1,%2};" : "=l"(r) : "f"(lo), "f"(hi));
    return r;
}
__device__ __forceinline__ void unpack2(unsigned long long v, float& lo, float& hi) {
    asm("mov.b64 {%0,%1}, %2;" : "=f"(lo), "=f"(hi) : "l"(v));
}
#define FMA2(d, a, b, c) \
    asm("fma.rn.f32x2 %0, %1, %2, %3;" : "=l"(d) : "l"(a), "l"(b), "l"(c))

// float bits -> order-preserving u32 key (handles negatives)
__device__ __forceinline__ unsigned fkey(float f) {
    unsigned b = __float_as_uint(f);
    return b ^ ((unsigned)((int)b >> 31) | 0x80000000u);
}
__device__ __forceinline__ float fkey_inv(unsigned t) {
    unsigned b = (t & 0x80000000u) ? (t ^ 0x80000000u) : ~t;
    return __uint_as_float(b);
}

// sorted top-20 as u64 keys (dist_key<<12 | idx). Index low bits REQUIRED for
// exact jax top_k tie semantics (R7 vs R8: value-only -> 3e-4, keyed -> 3e-7).
// Unique keys -> the 20 smallest form an order-invariant SET (verified R12),
// which legalizes replaying the 4 substacks in any order.
__device__ __forceinline__ void insert20k(unsigned long long k,
                                          unsigned long long (&val)[K_NN]) {
#pragma unroll
    for (int j = 0; j < K_NN; j++) {
        unsigned long long vj = val[j];
        bool lt = k < vj;
        val[j] = lt ? k : vj;     // keep smaller
        k      = lt ? vj : k;     // carry larger
    }
}

// exact reference-rounding distance from scaled point (px2=-2x etc.)
__device__ __forceinline__ float exact_d(float qx, float qy, float qz, float qw,
                                         float4 p) {
    float px = __fmul_rn(-0.5f, p.x);   // exact (power of two scale)
    float py = __fmul_rn(-0.5f, p.y);
    float pz = __fmul_rn(-0.5f, p.z);
    float t = __fadd_rn(__fadd_rn(__fmul_rn(qx, px), __fmul_rn(qy, py)),
                        __fmul_rn(qz, pz));
    return __fsub_rn(__fadd_rn(qw, p.w), __fmul_rn(2.0f, t));
}

// =============================================================================
// Kernel 1: per-batch exact KNN (one query/thread, 4096 candidates in smem)
// FUSED with fp64 BatchNorm moment accumulation (epilogue).
//
// Flat branch-free scan (the measured-fastest structure, R7/R9) with FOUR
// interleaved per-lane substacks: candidate m pushes to substack m&3, giving
// 4 independent addr/predicate dependency chains (the serial @p add.u32 addr
// chain through 4096 candidates was the hidden latency sink at 4 warps/SMSP).
// Guard per 32-group requires >=8 free slots per substack; each 32-group
// pushes exactly <=8 per substack -> overflow IMPOSSIBLE (no careful path,
// no rescan). Flush = exact recompute + u64 keyed insert + tau refresh.
// =============================================================================
__global__ void __launch_bounds__(512, 1)
knn_stats_kernel(const float* __restrict__ x) {
    extern __shared__ char smem_raw[];
    float4* pts = (float4*)smem_raw;                       // 64 KB
    char*   stacks = smem_raw + N_PTS * sizeof(float4);    // 16 warps * 8 KB = 128 KB

    const int b    = blockIdx.y;
    const int qblk = blockIdx.x;
    const float* xb = x + (size_t)b * N_PTS * 3;

    for (int i = threadIdx.x; i < N_PTS; i += 512) {
        float x0 = xb[i * 3 + 0], x1 = xb[i * 3 + 1], x2 = xb[i * 3 + 2];
        float sq = __fadd_rn(__fadd_rn(__fmul_rn(x0, x0), __fmul_rn(x1, x1)),
                             __fmul_rn(x2, x2));
        pts[i] = make_float4(__fmul_rn(-2.0f, x0), __fmul_rn(-2.0f, x1),
                             __fmul_rn(-2.0f, x2), sq);
    }
    __syncthreads();

    const int q = qblk * 512 + threadIdx.x;
    const float4 qp = pts[q];
    const float qx = __fmul_rn(-0.5f, qp.x);
    const float qy = __fmul_rn(-0.5f, qp.y);
    const float qz = __fmul_rn(-0.5f, qp.z);
    const float qw = qp.w;

    // four per-lane substacks: warp base + s*2KB, lane 4B offset, 128B stride
    unsigned a0, a1, a2, a3, l0, l1, l2, l3;
    {
        unsigned wb = (unsigned)__cvta_generic_to_shared(
                          stacks + (size_t)(threadIdx.x >> 5) * (4 * CAP_S * 128)) +
                      (threadIdx.x & 31) * 4;
        a0 = wb;        l0 = a0 + CAP_S * 128;
        a1 = wb + 2048; l1 = a1 + CAP_S * 128;
        a2 = wb + 4096; l2 = a2 + CAP_S * 128;
        a3 = wb + 6144; l3 = a3 + CAP_S * 128;
    }

    unsigned long long val[K_NN];
#pragma unroll
    for (int j = 0; j < K_NN; j++) val[j] = 0xFFFFFFFFFFFFFFFFull;

    // ---- init: candidates 0..19 unconditional, 20..31 gated (exact) ----
#pragma unroll 2
    for (int m = 0; m < K_NN; m++) {
        float d = exact_d(qx, qy, qz, qw, pts[m]);
        insert20k(((unsigned long long)fkey(d) << 12) | (unsigned)m, val);
    }
#pragma unroll 2
    for (int m = K_NN; m < 32; m++) {
        float d = exact_d(qx, qy, qz, qw, pts[m]);
        unsigned long long k = ((unsigned long long)fkey(d) << 12) | (unsigned)m;
        if (k < val[K_NN - 1]) insert20k(k, val);
    }
    float tau = fkey_inv((unsigned)(val[K_NN - 1] >> 12)) - qw + SLACK;

#define PUSH(A, M) do {                                                       \
    float4 _p = pts[M];                                                       \
    float _ds = fmaf(_p.x, qx, fmaf(_p.y, qy, fmaf(_p.z, qz, _p.w)));         \
    asm volatile(                                                             \
        "{\n\t.reg .pred p;\n\t"                                              \
        "setp.lt.f32 p, %1, %2;\n\t"                                          \
        "@p st.shared.b32 [%0], %3;\n\t"                                      \
        "@p add.u32 %0, %0, 128;\n\t}"                                        \
        : "+r"(A) : "f"(_ds), "f"(tau), "r"(M));                              \
} while (0)

#define FLUSH_SUB(A, LIM) do {                                                \
    const unsigned _base = (LIM) - CAP_S * 128;                               \
    for (unsigned _pp = _base; _pp < (A); _pp += 128) {                       \
        unsigned _m;                                                          \
        asm volatile("ld.shared.b32 %0, [%1];" : "=r"(_m) : "r"(_pp));        \
        float _d = exact_d(qx, qy, qz, qw, pts[_m]);                          \
        unsigned long long _k =                                               \
            ((unsigned long long)fkey(_d) << 12) | _m;                        \
        if (_k < val[K_NN - 1]) insert20k(_k, val);                           \
    }                                                                         \
    (A) = _base;                                                              \
} while (0)

#define FLUSH_ALL() do {                                                      \
    FLUSH_SUB(a0, l0); FLUSH_SUB(a1, l1);                                     \
    FLUSH_SUB(a2, l2); FLUSH_SUB(a3, l3);                                     \
    tau = fkey_inv((unsigned)(val[K_NN - 1] >> 12)) - qw + SLACK;             \
} while (0)

    static const short bnd[NCHUNK] = {
        64, 96, 128, 192, 256, 352, 480, 672,
        928, 1280, 1792, 2464, 3392, 4096};

    int lo = 32;
#pragma unroll 1
    for (int c = 0; c < NCHUNK; c++) {
        const int hi = bnd[c];
#pragma unroll 1
        for (int g = lo; g < hi; g += 32) {
            // headroom guard: each 32-group pushes <=8 per substack
            bool near = (a0 + 8u * 128u > l0) | (a1 + 8u * 128u > l1) |
                        (a2 + 8u * 128u > l2) | (a3 + 8u * 128u > l3);
            if (__any_sync(0xFFFFFFFFu, near)) FLUSH_ALL();
#pragma unroll 2
            for (int mm = 0; mm < 32; mm += 4) {
                PUSH(a0, g + mm + 0);
                PUSH(a1, g + mm + 1);
                PUSH(a2, g + mm + 2);
                PUSH(a3, g + mm + 3);
            }
        }
        FLUSH_ALL();                                 // chunk boundary: tau refresh
        lo = hi;
    }
#undef PUSH
#undef FLUSH_SUB
#undef FLUSH_ALL

    // ---- write indices ----
    int* op = g_idx + ((size_t)(b * N_PTS) + q) * K_NN;
#pragma unroll
    for (int j = 0; j < K_NN; j++) op[j] = (int)(val[j] & 0xFFFu);

    // ================= fused BN moment epilogue =================
    const float qix = qx, qiy = qy, qiz = qz;
    float sj0 = 0, sj1 = 0, sj2 = 0;
    float jj00 = 0, jj01 = 0, jj02 = 0, jj11 = 0, jj12 = 0, jj22 = 0;
    float ij00 = 0, ij01 = 0, ij02 = 0, ij10 = 0, ij11 = 0, ij12 = 0,
          ij20 = 0, ij21 = 0, ij22 = 0;
#pragma unroll
    for (int j = 0; j < K_NN; j++) {
        float4 p = pts[val[j] & 0xFFFu];
        float pxx = -0.5f * p.x, pyy = -0.5f * p.y, pzz = -0.5f * p.z;
        sj0 += pxx; sj1 += pyy; sj2 += pzz;
        jj00 = fmaf(pxx, pxx, jj00); jj01 = fmaf(pxx, pyy, jj01);
        jj02 = fmaf(pxx, pzz, jj02); jj11 = fmaf(pyy, pyy, jj11);
        jj12 = fmaf(pyy, pzz, jj12); jj22 = fmaf(pzz, pzz, jj22);
        ij00 = fmaf(qix, pxx, ij00); ij01 = fmaf(qix, pyy, ij01);
        ij02 = fmaf(qix, pzz, ij02); ij10 = fmaf(qiy, pxx, ij10);
        ij11 = fmaf(qiy, pyy, ij11); ij12 = fmaf(qiy, pzz, ij12);
        ij20 = fmaf(qiz, pxx, ij20); ij21 = fmaf(qiz, pyy, ij21);
        ij22 = fmaf(qiz, pzz, ij22);
    }

    double vals[NVALS] = {
        (double)qix, (double)qiy, (double)qiz,
        (double)qix * qix, (double)qix * qiy, (double)qix * qiz,
        (double)qiy * qiy, (double)qiy * qiz, (double)qiz * qiz,
        (double)sj0, (double)sj1, (double)sj2,
        (double)jj00, (double)jj01, (double)jj02,
        (double)jj11, (double)jj12, (double)jj22,
        (double)ij00, (double)ij01, (double)ij02,
        (double)ij10, (double)ij11, (double)ij12,
        (double)ij20, (double)ij21, (double)ij22
    };

    __syncthreads();                       // stacks no longer needed
    double* wsum = (double*)stacks;        // [16][NVALS], aliases stacks
    const int wid = threadIdx.x >> 5;
    const int lid = threadIdx.x & 31;
#pragma unroll
    for (int v = 0; v < NVALS; v++) {
        double s = vals[v];
#pragma unroll
        for (int o = 16; o > 0; o >>= 1) s += __shfl_xor_sync(0xFFFFFFFFu, s, o);
        if (lid == 0) wsum[wid * NVALS + v] = s;
    }
    __syncthreads();
    if (threadIdx.x < NVALS) {
        double s = 0.0;
#pragma unroll
        for (int w = 0; w < 16; w++) s += wsum[w * NVALS + threadIdx.x];
        g_part[(blockIdx.y * gridDim.x + blockIdx.x) * NVALS + threadIdx.x] = s;
    }
}

// =============================================================================
// Kernel 2: finalize BN stats -> per-channel scale/shift (fp64 math).
// =============================================================================
__global__ void __launch_bounds__(864, 1)
finalize_kernel(const float* __restrict__ w1,
                const float* __restrict__ b1,
                const float* __restrict__ gamma,
                const float* __restrict__ beta) {
    __shared__ double S[NVALS];
    const int wid = threadIdx.x >> 5;
    const int lid = threadIdx.x & 31;
    if (wid < NVALS) {
        double s = 0.0;
#pragma unroll
        for (int r = 0; r < KNN_BLOCKS / 32; r++)
            s += g_part[(r * 32 + lid) * NVALS + wid];
#pragma unroll
        for (int o = 16; o > 0; o >>= 1) s += __shfl_xor_sync(0xFFFFFFFFu, s, o);
        if (lid == 0) S[wid] = s;
    }
    __syncthreads();
    if (threadIdx.x >= CO) return;

    const int c = threadIdx.x;
    const double M = (double)B_SZ * N_PTS * K_NN;
    const double Kd = (double)K_NN;

    double q0 = (double)w1[3 * CO + c], q1 = (double)w1[4 * CO + c], q2 = (double)w1[5 * CO + c];
    double p0 = (double)w1[0 * CO + c] - q0;
    double p1 = (double)w1[1 * CO + c] - q1;
    double p2 = (double)w1[2 * CO + c] - q2;
    double s_ = (double)b1[c];

    double Si0 = Kd * S[0], Si1 = Kd * S[1], Si2 = Kd * S[2];
    double i00 = Kd * S[3], i01 = Kd * S[4], i02 = Kd * S[5];
    double i11 = Kd * S[6], i12 = Kd * S[7], i22 = Kd * S[8];
    double Sj0 = S[9], Sj1 = S[10], Sj2 = S[11];
    double j00 = S[12], j01 = S[13], j02 = S[14], j11 = S[15], j12 = S[16], j22 = S[17];

    double pSi = p0 * Si0 + p1 * Si1 + p2 * Si2;
    double qSj = q0 * Sj0 + q1 * Sj1 + q2 * Sj2;
    double mean = (pSi + qSj) / M + s_;

    double pMp = p0 * p0 * i00 + p1 * p1 * i11 + p2 * p2 * i22 +
                 2.0 * (p0 * p1 * i01 + p0 * p2 * i02 + p1 * p2 * i12);
    double qMq = q0 * q0 * j00 + q1 * q1 * j11 + q2 * q2 * j22 +
                 2.0 * (q0 * q1 * j01 + q0 * q2 * j02 + q1 * q2 * j12);
    double pMq = p0 * (q0 * S[18] + q1 * S[19] + q2 * S[20]) +
                 p1 * (q0 * S[21] + q1 * S[22] + q2 * S[23]) +
                 p2 * (q0 * S[24] + q1 * S[25] + q2 * S[26]);

    double sumsq = pMp + qMq + 2.0 * pMq + 2.0 * s_ * (pSi + qSj) + M * s_ * s_;
    double var = sumsq / M - mean * mean;
    double rstd = 1.0 / sqrt(var + 1e-5);

    double g = (double)gamma[c];
    g_scale[c] = (float)(g * rstd);
    g_shift[c] = (float)((double)beta[c] - mean * g * rstd);
}

// =============================================================================
// Kernel 3: fused edge-MLP + BN + ReLU + (r @ w2) + max over K.
// One warp per point, 2 channels/lane. At the FFMA2 structural roofline.
// =============================================================================
__global__ void __launch_bounds__(256, 3)
main_kernel(const float* __restrict__ x,
            const float* __restrict__ w1,
            const float* __restrict__ b1,
            const float* __restrict__ w2,
            const float* __restrict__ b2,
            float* __restrict__ out) {
    extern __shared__ float sm[];
    float2* w2p = (float2*)sm;             // [64][32] float2
    float*  rt  = sm + CO * CO;            // 8 warps * 64 * 20

    for (int i = threadIdx.x; i < CO * 32; i += blockDim.x) {
        int c = i >> 5, l = i & 31;
        w2p[i] = make_float2(w2[c * CO + l], w2[c * CO + l + 32]);
    }
    __syncthreads();

    const int w = threadIdx.x >> 5;
    const int l = threadIdx.x & 31;
    const int pt = blockIdx.x * 8 + w;
    float* rw = rt + w * (CO * K_NN);

    const int ca = l, cb = l + 32;

    float wja[3], wjb[3], wia[3], wib[3];
#pragma unroll
    for (int r = 0; r < 3; r++) {
        float a0 = __ldg(w1 + r * CO + ca);
        float a3 = __ldg(w1 + (r + 3) * CO + ca);
        float b0 = __ldg(w1 + r * CO + cb);
        float b3 = __ldg(w1 + (r + 3) * CO + cb);
        wja[r] = a3; wjb[r] = b3;
        wia[r] = a0 - a3; wib[r] = b0 - b3;
    }
    const float b1a = __ldg(b1 + ca), b1b = __ldg(b1 + cb);
    const float sca = g_scale[ca], scb = g_scale[cb];
    const float sha = g_shift[ca], shb = g_shift[cb];

    const int b = pt >> 12;
    const int gbase = b << 12;
    const float* xr = x + (size_t)pt * 3;
    const float xi0 = __ldg(xr), xi1 = __ldg(xr + 1), xi2 = __ldg(xr + 2);
    const int* ip = g_idx + (size_t)pt * K_NN;

    const float basea = fmaf(xi2, wia[2], fmaf(xi1, wia[1], fmaf(xi0, wia[0], b1a)));
    const float baseb = fmaf(xi2, wib[2], fmaf(xi1, wib[1], fmaf(xi0, wib[0], b1b)));

    // ---- stage 1: r[c][k] = relu(scale*h + shift) ----
#pragma unroll 4
    for (int k = 0; k < K_NN; k++) {
        int j = __ldg(ip + k);
        const float* xp = x + (size_t)(gbase + j) * 3;
        float j0 = __ldg(xp), j1 = __ldg(xp + 1), j2 = __ldg(xp + 2);

        float ha = fmaf(j2, wja[2], fmaf(j1, wja[1], fmaf(j0, wja[0], basea)));
        float hb = fmaf(j2, wjb[2], fmaf(j1, wjb[1], fmaf(j0, wjb[0], baseb)));

        rw[ca * K_NN + k] = fmaxf(fmaf(ha, sca, sha), 0.0f);
        rw[cb * K_NN + k] = fmaxf(fmaf(hb, scb, shb), 0.0f);
    }
    __syncwarp();

    // ---- stage 2: packed FFMA2 GEMM, acc[i] holds k=(2i, 2i+1) ----
    unsigned long long acca[K_NN / 2], accb[K_NN / 2];
#pragma unroll
    for (int i = 0; i < K_NN / 2; i++) { acca[i] = 0ULL; accb[i] = 0ULL; }

#pragma unroll 4
    for (int c = 0; c < CO; c++) {
        float2 wab = w2p[c * 32 + l];
        unsigned long long wa2 = pack2(wab.x, wab.x);
        unsigned long long wb2 = pack2(wab.y, wab.y);
        const ulonglong2* r2 = (const ulonglong2*)(rw + c * K_NN);
#pragma unroll
        for (int t = 0; t < 5; t++) {
            ulonglong2 rv = r2[t];
            FMA2(acca[2 * t],     rv.x, wa2, acca[2 * t]);
            FMA2(acca[2 * t + 1], rv.y, wa2, acca[2 * t + 1]);
            FMA2(accb[2 * t],     rv.x, wb2, accb[2 * t]);
            FMA2(accb[2 * t + 1], rv.y, wb2, accb[2 * t + 1]);
        }
    }

    float ma = -3.402823466e38f, mb = -3.402823466e38f;
#pragma unroll
    for (int i = 0; i < K_NN / 2; i++) {
        float a0, a1, b0, b1v;
        unpack2(acca[i], a0, a1);
        unpack2(accb[i], b0, b1v);
        ma = fmaxf(ma, fmaxf(a0, a1));
        mb = fmaxf(mb, fmaxf(b0, b1v));
    }

    out[(size_t)pt * CO + ca] = ma + __ldg(b2 + ca);
    out[(size_t)pt * CO + cb] = mb + __ldg(b2 + cb);
}

// =============================================================================
extern "C" void kernel_launch(void* const* d_in, const int* in_sizes, int n_in,
                              void* d_out, int out_size) {
    const float* x     = (const float*)d_in[0];
    // d_in[1] = batch indices (implied by layout; unused)
    const float* w1    = (const float*)d_in[2];
    const float* b1    = (const float*)d_in[3];
    const float* gamma = (const float*)d_in[4];
    const float* beta  = (const float*)d_in[5];
    const float* w2    = (const float*)d_in[6];
    const float* b2    = (const float*)d_in[7];
    float* out = (float*)d_out;

    const int knn_smem  = N_PTS * sizeof(float4) + 16 * 4 * CAP_S * 128;   // 192 KB
    const int main_smem = (CO * CO + 8 * CO * K_NN) * sizeof(float);       // 56 KB

    cudaFuncSetAttribute(knn_stats_kernel, cudaFuncAttributeMaxDynamicSharedMemorySize, knn_smem);
    cudaFuncSetAttribute(main_kernel,      cudaFuncAttributeMaxDynamicSharedMemorySize, main_smem);

    knn_stats_kernel<<<dim3(8, B_SZ), 512, knn_smem>>>(x);
    finalize_kernel<<<1, 864>>>(w1, b1, gamma, beta);
    main_kernel<<<(B_SZ * N_PTS) / 8, 256, main_smem>>>(x, w1, b1, w2, b2, out);
}